// round 17
// baseline (speedup 1.0000x reference)
#include <cuda_runtime.h>
#include <cuda_fp16.h>
#include <cstdint>

#define B_DIM 4096
#define T_DIM 200
#define NEG_INF (-4294967295.0f)

// smem byte offsets
#define OFF_K    0        // fp32 keys 200 x 256B, 16B-chunk XOR swizzle (c ^ (r&7))
#define OFF_WT   51200    // weight tables hi[4608B] + lo[4608B]
#define OFF_QH   60416    // f32 qh[32]
#define OFF_W2   60544    // f32 w2[32]
#define OFF_SC   60672    // f32 scores[200] (pad 832)
#define OFF_RED  61504    // f32 red[32]: [0..15] lmax, [16..31] lsum
#define OFF_OP   61632    // float2 opart[16][32]
#define SMEM_BYTES 65728

__device__ float    g_wq[2048];    // W1a + W1c
__device__ uint32_t g_wtab[2304];  // [0,1152): f16x2 hi fragments; [1152,2304): lo
__device__ int      g_mode;        // 1 = mask is u8, 0 = int32

__global__ __launch_bounds__(256)
void setup_kernel(const float* __restrict__ W1,
                  const unsigned char* __restrict__ mask_raw)
{
    const int tid = threadIdx.x, blk = blockIdx.x;
    if (blk < 8) {
        const int i = blk * 256 + tid;
        g_wq[i] = W1[i] + W1[4096 + i];
        return;
    }
    if (blk == 12) {
        const uint32_t* mw = (const uint32_t*)mask_raw;
        uint32_t nz = mw[tid] & 0xFFFFFF00u;
        if (__syncthreads_or(nz != 0)) { if (tid == 0) g_mode = 1; }
        else                           { if (tid == 0) g_mode = 0; }
        return;
    }
    const int idx = (blk - 8) * 256 + tid;
    int d2 = idx >> 5, j = idx & 31, k = 2 * d2;
    float w0 = W1[2048 + k * 32 + j] - W1[4096 + k * 32 + j];
    float w1 = W1[2048 + (k + 1) * 32 + j] - W1[4096 + (k + 1) * 32 + j];
    uint32_t hi, lo;
    asm("cvt.rn.f16x2.f32 %0, %1, %2;" : "=r"(hi) : "f"(w1), "f"(w0));
    float h0f = __half2float(__ushort_as_half((unsigned short)(hi & 0xFFFFu)));
    float h1f = __half2float(__ushort_as_half((unsigned short)(hi >> 16)));
    asm("cvt.rn.f16x2.f32 %0, %1, %2;" : "=r"(lo) : "f"(w1 - h1f), "f"(w0 - h0f));
    int ks = d2 >> 3, k2 = d2 & 7, t4 = k2 & 3, sel = k2 >> 2;
    int word = ks * 288 + t4 * 72 + j * 2 + sel;
    g_wtab[word]        = hi;
    g_wtab[1152 + word] = lo;
}

__global__ __launch_bounds__(512, 2)
void attn_pool_kernel(const float* __restrict__ query,
                      const float* __restrict__ keys,
                      const unsigned char* __restrict__ mask_raw,
                      const float* __restrict__ b1,
                      const float* __restrict__ W2,
                      const float* __restrict__ b2,
                      float* __restrict__ out)
{
    extern __shared__ char sm[];
    float* smf = (float*)sm;
    const int b    = blockIdx.x;
    const int tid  = threadIdx.x;
    const int lane = tid & 31;
    const int wid  = tid >> 5;       // 0..15
    const int g    = lane >> 2;
    const int t4   = lane & 3;
    uint32_t sbase;
    asm("{ .reg .u64 t; cvta.to.shared.u64 t, %1; cvt.u32.u64 %0, t; }"
        : "=r"(sbase) : "l"(sm));
    const char* kbg = (const char*)(keys + (size_t)b * 12800);

    // ---- stage fp32 keys via cp.async (XOR chunk swizzle) + weight tables ----
    #pragma unroll
    for (int i = tid; i < 3200; i += 512) {
        int r = i >> 4, c = i & 15;
        asm volatile("cp.async.cg.shared.global [%0], [%1], 16;"
                     :: "r"(sbase + OFF_K + r * 256 + ((c ^ (r & 7)) << 4)),
                        "l"(kbg + i * 16));
    }
    #pragma unroll
    for (int i = tid; i < 576; i += 512)
        asm volatile("cp.async.cg.shared.global [%0], [%1], 16;"
                     :: "r"(sbase + OFF_WT + i * 16), "l"((const char*)g_wtab + i * 16));
    asm volatile("cp.async.commit_group;" ::: "memory");

    // ---- warp 13: qh chain ; warp 14: w2 ----
    if (wid == 13) {
        float q0 = query[(size_t)b * 64 + lane];
        float q1 = query[(size_t)b * 64 + 32 + lane];
        float s = b1[lane];
        #pragma unroll
        for (int d = 0; d < 32; d++)
            s = fmaf(__shfl_sync(0xffffffffu, q0, d), g_wq[d * 32 + lane], s);
        #pragma unroll
        for (int d = 0; d < 32; d++)
            s = fmaf(__shfl_sync(0xffffffffu, q1, d), g_wq[(32 + d) * 32 + lane], s);
        smf[OFF_QH / 4 + lane] = s;
    }
    if (wid == 14) smf[OFF_W2 / 4 + lane] = __ldg(W2 + lane);

    // ---- mask bits (precomputed dtype) + b2 ----
    const bool mode_u8 = (g_mode != 0);
    const int* mask_i32 = (const int*)mask_raw;
    const float b2v = __ldg(b2);

    int mval = 0;
    if (t4 == 0 && wid < 13) {
        const int r0 = wid * 16 + g, r1 = r0 + 8;
        bool v0 = mode_u8 ? (mask_raw[b * T_DIM + r0] != 0)
                          : (mask_i32[b * T_DIM + r0] != 0);
        mval = (int)v0;
        if (r1 < T_DIM) {
            bool v1 = mode_u8 ? (mask_raw[b * T_DIM + r1] != 0)
                              : (mask_i32[b * T_DIM + r1] != 0);
            mval |= (int)v1 << 1;
        }
    }

    asm volatile("cp.async.wait_group 0;" ::: "memory");
    __syncthreads();

    // ====== score GEMM: one m16 tile per warp (warps 0..12) ======
    if (wid < 13) {
        const int m0 = wid * 16;
        float acc[4][4];
        #pragma unroll
        for (int nt = 0; nt < 4; nt++)
            #pragma unroll
            for (int e = 0; e < 4; e++) acc[nt][e] = 0.0f;

        const bool r1ok = (m0 + g + 8) < T_DIM;
        const uint32_t base0 = sbase + OFF_K +
                               (uint32_t)((m0 + g) * 256 + ((t4 & 1) << 3));
        #pragma unroll
        for (int ks = 0; ks < 4; ks++) {
            const uint32_t wrow = sbase + OFF_WT + (uint32_t)(ks * 1152 + t4 * 288 + g * 8);
            uint2 bh[4], bl[4];
            #pragma unroll
            for (int nt = 0; nt < 4; nt++) {
                asm("ld.shared.v2.u32 {%0,%1},[%2];"
                    : "=r"(bh[nt].x), "=r"(bh[nt].y) : "r"(wrow + nt * 64));
                asm("ld.shared.v2.u32 {%0,%1},[%2];"
                    : "=r"(bl[nt].x), "=r"(bl[nt].y) : "r"(wrow + nt * 64 + 4608));
            }
            const int c0 = 4 * ks + (t4 >> 1);
            const uint32_t o0 = (uint32_t)((c0 ^ g) << 4);
            const uint32_t o2 = (uint32_t)(((c0 + 2) ^ g) << 4);
            float2 A0, A2;
            asm("ld.shared.v2.f32 {%0,%1},[%2];" : "=f"(A0.x), "=f"(A0.y) : "r"(base0 + o0));
            asm("ld.shared.v2.f32 {%0,%1},[%2];" : "=f"(A2.x), "=f"(A2.y) : "r"(base0 + o2));
            uint32_t a0, a1, a2, a3;
            asm("cvt.rn.f16x2.f32 %0,%1,%2;" : "=r"(a0) : "f"(A0.y), "f"(A0.x));
            asm("cvt.rn.f16x2.f32 %0,%1,%2;" : "=r"(a2) : "f"(A2.y), "f"(A2.x));
            if (r1ok) {
                float2 A1, A3;
                asm("ld.shared.v2.f32 {%0,%1},[%2];"
                    : "=f"(A1.x), "=f"(A1.y) : "r"(base0 + 2048 + o0));
                asm("ld.shared.v2.f32 {%0,%1},[%2];"
                    : "=f"(A3.x), "=f"(A3.y) : "r"(base0 + 2048 + o2));
                asm("cvt.rn.f16x2.f32 %0,%1,%2;" : "=r"(a1) : "f"(A1.y), "f"(A1.x));
                asm("cvt.rn.f16x2.f32 %0,%1,%2;" : "=r"(a3) : "f"(A3.y), "f"(A3.x));
            } else { a1 = 0u; a3 = 0u; }
            #pragma unroll
            for (int nt = 0; nt < 4; nt++) {
                asm volatile(
                    "mma.sync.aligned.m16n8k16.row.col.f32.f16.f16.f32 "
                    "{%0,%1,%2,%3}, {%4,%5,%6,%7}, {%8,%9}, {%0,%1,%2,%3};"
                    : "+f"(acc[nt][0]), "+f"(acc[nt][1]), "+f"(acc[nt][2]), "+f"(acc[nt][3])
                    : "r"(a0), "r"(a1), "r"(a2), "r"(a3), "r"(bh[nt].x), "r"(bh[nt].y));
                asm volatile(
                    "mma.sync.aligned.m16n8k16.row.col.f32.f16.f16.f32 "
                    "{%0,%1,%2,%3}, {%4,%5,%6,%7}, {%8,%9}, {%0,%1,%2,%3};"
                    : "+f"(acc[nt][0]), "+f"(acc[nt][1]), "+f"(acc[nt][2]), "+f"(acc[nt][3])
                    : "r"(a0), "r"(a1), "r"(a2), "r"(a3), "r"(bl[nt].x), "r"(bl[nt].y));
            }
        }

        // ---- epilogue: 4-way batched-reciprocal sigmoid, dot W2, t4-reduce, mask ----
        float s_lo = 0.0f, s_hi = 0.0f;
        #pragma unroll
        for (int nt = 0; nt < 4; nt++) {
            const int j0 = 8 * nt + 2 * t4;
            float2 qh2 = *(float2*)(sm + OFF_QH + j0 * 4);
            float2 w22 = *(float2*)(sm + OFF_W2 + j0 * 4);
            float p0 = 1.0f + __expf(-(acc[nt][0] + qh2.x));
            float p1 = 1.0f + __expf(-(acc[nt][1] + qh2.y));
            float p2 = 1.0f + __expf(-(acc[nt][2] + qh2.x));
            float p3 = 1.0f + __expf(-(acc[nt][3] + qh2.y));
            float d01 = p0 * p1, d23 = p2 * p3;
            float r = __fdividef(1.0f, d01 * d23);
            float rd23 = r * d23, rd01 = r * d01;
            s_lo = fmaf(rd23 * p1, w22.x, s_lo);   // sigma0 = p1*d23/r_total
            s_lo = fmaf(rd23 * p0, w22.y, s_lo);
            s_hi = fmaf(rd01 * p3, w22.x, s_hi);
            s_hi = fmaf(rd01 * p2, w22.y, s_hi);
        }
        s_lo += __shfl_xor_sync(0xffffffffu, s_lo, 1);
        s_lo += __shfl_xor_sync(0xffffffffu, s_lo, 2);
        s_hi += __shfl_xor_sync(0xffffffffu, s_hi, 1);
        s_hi += __shfl_xor_sync(0xffffffffu, s_hi, 2);
        if (t4 == 0) {
            const int r0 = m0 + g, r1 = r0 + 8;
            smf[OFF_SC / 4 + r0] = (mval & 1) ? (s_lo + b2v) : NEG_INF;
            if (r1 < T_DIM)
                smf[OFF_SC / 4 + r1] = (mval & 2) ? (s_hi + b2v) : NEG_INF;
        }
    }
    __syncthreads();

    // ---- fused online softmax + weighted partial: warp owns keys [13w, 13w+13) ----
    const int t0 = wid * 13;
    float sc = (lane < 13 && (t0 + lane) < T_DIM) ? smf[OFF_SC / 4 + t0 + lane] : -1e38f;
    float lmax = sc;
    #pragma unroll
    for (int o = 16; o; o >>= 1) lmax = fmaxf(lmax, __shfl_xor_sync(0xffffffffu, lmax, o));
    float e = (lane < 13) ? __expf(sc - lmax) : 0.0f;
    float lsum = e;
    #pragma unroll
    for (int o = 16; o; o >>= 1) lsum += __shfl_xor_sync(0xffffffffu, lsum, o);
    if (lane == 0) {
        smf[OFF_RED / 4 + wid] = lmax;
        smf[OFF_RED / 4 + 16 + wid] = lsum;
    }
    // weighted partial from fp32 swizzled keys; lane owns d-pair (2lane, 2lane+1)
    float ax = 0.0f, ay = 0.0f;
    #pragma unroll
    for (int t = 0; t < 13; t++) {
        const int tt = t0 + t;
        float p = __shfl_sync(0xffffffffu, e, t);
        if (tt < T_DIM) {
            float kx, ky;
            asm("ld.shared.v2.f32 {%0,%1},[%2];"
                : "=f"(kx), "=f"(ky)
                : "r"(sbase + OFF_K + tt * 256 + ((((uint32_t)(lane >> 1)) ^ (tt & 7)) << 4)
                      + ((lane & 1) << 3)));
            ax = fmaf(p, kx, ax);
            ay = fmaf(p, ky, ay);
        }
    }
    __syncthreads();

    // ---- global combine (16-lane parallel), scale, store partials ----
    {
        float rv = (lane < 16) ? smf[OFF_RED / 4 + lane] : -1e38f;
        float gm = rv;
        #pragma unroll
        for (int o = 16; o; o >>= 1) gm = fmaxf(gm, __shfl_xor_sync(0xffffffffu, gm, o));
        float term = (lane < 16) ? smf[OFF_RED / 4 + 16 + lane] * __expf(rv - gm) : 0.0f;
        float gs = term;
        #pragma unroll
        for (int o = 16; o; o >>= 1) gs += __shfl_xor_sync(0xffffffffu, gs, o);
        float scale = __expf(lmax - gm) * __fdividef(1.0f, gs);
        *(float2*)(sm + OFF_OP + wid * 256 + lane * 8) =
            make_float2(ax * scale, ay * scale);
    }
    __syncthreads();
    if (tid < 64) {
        float r = 0.0f;
        #pragma unroll
        for (int p = 0; p < 16; p++)
            r += smf[OFF_OP / 4 + p * 64 + tid];
        out[(size_t)b * 64 + tid] = r;
    }
}

extern "C" void kernel_launch(void* const* d_in, const int* in_sizes, int n_in,
                              void* d_out, int out_size)
{
    const float*         query = (const float*)d_in[0];
    const float*         keys  = (const float*)d_in[1];
    const unsigned char* mask  = (const unsigned char*)d_in[2];
    const float*         W1    = (const float*)d_in[3];
    const float*         b1    = (const float*)d_in[4];
    const float*         W2    = (const float*)d_in[5];
    const float*         b2    = (const float*)d_in[6];
    float* out = (float*)d_out;

    setup_kernel<<<13, 256>>>(W1, mask);
    cudaFuncSetAttribute(attn_pool_kernel,
                         cudaFuncAttributeMaxDynamicSharedMemorySize, SMEM_BYTES);
    attn_pool_kernel<<<B_DIM, 512, SMEM_BYTES>>>(query, keys, mask, b1, W2, b2, out);
}